// round 4
// baseline (speedup 1.0000x reference)
#include <cuda_runtime.h>
#include <cuda_bf16.h>

// HopfieldTSP: x_1000 = sign(w @ x0). Iterations 2..1000 are a provable fixed
// point (diagonal 2*rowsum_i ~ 8192 dominates |sum_j adj_ij*(+-1)| <= rowsum_i),
// so one fused pass computes rowsum_i and dot_i = (adj@x0)_i, then
//   s_i = (2*rowsum_i + adj_ii)*x0_i - dot_i ;  out_i = sign(s_i).
//
// R3: kill the block-granularity tail. Grid = 148*4 = 592 blocks (one exact
// wave at 4 blocks/SM, 100% occ) and work is striped at HALF-ROW granularity
// (16384 tasks x 16KB) across the 9472 warps: per-SM overload drops from +16%
// (4-vs-3 blocks) to +1.2%. Halves combine via deterministic global partials
// + per-row arrival counter (self-resetting for graph replay).

#define N_CITIES 8192
#define THREADS 512
#define WPB (THREADS / 32)          // 16 warps per block
#define NBLK (148 * 4)              // 592 — one exact full-occupancy wave
#define NWARP (NBLK * WPB)          // 9472 warps
#define NTASK (N_CITIES * 2)        // 16384 half-row tasks
#define HALF4 (N_CITIES / 8)        // 1024 float4 per half-row

__device__ float2 g_part[NTASK];    // (rowsum, dot) per half-row
__device__ int    g_cnt[N_CITIES];  // arrival counters; zero at load, self-restored

__global__ void __launch_bounds__(THREADS, 4)
hopfield_fused_kernel(const float* __restrict__ adj,
                      const float* __restrict__ x,
                      float* __restrict__ out) {
    __shared__ float xs[N_CITIES];  // 32 KB, shared by 16 warps, reused across tasks

    const float4* x4 = reinterpret_cast<const float4*>(x);
    float4* xs4 = reinterpret_cast<float4*>(xs);
    #pragma unroll
    for (int i = threadIdx.x; i < N_CITIES / 4; i += THREADS) {
        xs4[i] = x4[i];
    }
    __syncthreads();

    const int warp = threadIdx.x >> 5;
    const int lane = threadIdx.x & 31;
    const int gw   = blockIdx.x * WPB + warp;

    // Static stripe: warp gw handles tasks gw, gw+9472 (1 or 2 tasks).
    for (int t = gw; t < NTASK; t += NWARP) {
        const int row  = t >> 1;
        const int half = t & 1;

        const float4* arow = reinterpret_cast<const float4*>(
                                 adj + (size_t)row * N_CITIES) + half * HALF4;
        const float4* xh = xs4 + half * HALF4;

        float rs = 0.0f, dot = 0.0f;
        #pragma unroll 4
        for (int j = lane; j < HALF4; j += 32) {
            float4 a  = arow[j];
            float4 xv = xh[j];
            rs  += (a.x + a.y) + (a.z + a.w);
            dot += a.x * xv.x + a.y * xv.y + a.z * xv.z + a.w * xv.w;
        }

        #pragma unroll
        for (int o = 16; o > 0; o >>= 1) {
            rs  += __shfl_xor_sync(0xFFFFFFFFu, rs, o);
            dot += __shfl_xor_sync(0xFFFFFFFFu, dot, o);
        }

        if (lane == 0) {
            g_part[t] = make_float2(rs, dot);
            __threadfence();                       // publish partial
            int old = atomicAdd(&g_cnt[row], 1);
            if (old == 1) {                        // second arriver combines
                __threadfence();                   // acquire peer's partial
                volatile float* p = reinterpret_cast<volatile float*>(&g_part[2 * row]);
                float rsT  = p[0] + p[2];
                float dotT = p[1] + p[3];
                float aii  = __ldg(adj + (size_t)row * N_CITIES + row);
                float xi   = xs[row];
                float s    = (2.0f * rsT + aii) * xi - dotT;
                out[row] = (s > 0.0f) ? 1.0f : ((s < 0.0f) ? -1.0f : 0.0f);
                g_cnt[row] = 0;                    // restore for next graph replay
            }
        }
    }
}

extern "C" void kernel_launch(void* const* d_in, const int* in_sizes, int n_in,
                              void* d_out, int out_size) {
    const float* adj = (const float*)d_in[0];   // [8192, 8192] fp32 row-major
    const float* x   = (const float*)d_in[1];   // [8192] fp32
    float* out       = (float*)d_out;           // [8192] fp32

    hopfield_fused_kernel<<<NBLK, THREADS>>>(adj, x, out);
}

// round 5
// speedup vs baseline: 1.0098x; 1.0098x over previous
#include <cuda_runtime.h>
#include <cuda_bf16.h>

// HopfieldTSP: x_1000 = sign(w @ x0). Iterations 2..1000 are a provable fixed
// point (diagonal 2*rowsum_i ~ 8192 dominates |sum_j adj_ij*(+-1)| <= rowsum_i),
// so one fused pass computes rowsum_i and dot_i = (adj@x0)_i, then
//   s_i = (2*rowsum_i + adj_ii)*x0_i - dot_i ;  out_i = sign(s_i).
//
// R5: decouple occupancy from x-staging. No smem: x via __ldg (stays hot in
// L1 because the adj stream uses __ldcs evict-first). 256-thread blocks,
// one FULL row per warp (zero warp-level work quantization), 8 blocks/SM,
// grid 1024 <= capacity 1184 -> one wave, 7-vs-6 block tail = +1.2% only.

#define N_CITIES 8192
#define THREADS 256
#define ROWS_PER_BLOCK (THREADS / 32)   // 8
#define ROW4 (N_CITIES / 4)             // 2048 float4 per row

__global__ void __launch_bounds__(THREADS, 8)
hopfield_fused_kernel(const float* __restrict__ adj,
                      const float* __restrict__ x,
                      float* __restrict__ out) {
    const int warp = threadIdx.x >> 5;
    const int lane = threadIdx.x & 31;
    const int row  = blockIdx.x * ROWS_PER_BLOCK + warp;

    const float4* arow = reinterpret_cast<const float4*>(adj + (size_t)row * N_CITIES);
    const float4* x4   = reinterpret_cast<const float4*>(x);

    // 64 trips per lane. adj: streaming (evict-first) so it never evicts x
    // from L1; x: read-only path, hot in L1 after first touch.
    float rs = 0.0f, dot = 0.0f;
    #pragma unroll 2
    for (int j = lane; j < ROW4; j += 32) {
        float4 a  = __ldcs(&arow[j]);
        float4 xv = __ldg(&x4[j]);
        rs  += (a.x + a.y) + (a.z + a.w);
        dot += a.x * xv.x + a.y * xv.y + a.z * xv.z + a.w * xv.w;
    }

    #pragma unroll
    for (int o = 16; o > 0; o >>= 1) {
        rs  += __shfl_xor_sync(0xFFFFFFFFu, rs, o);
        dot += __shfl_xor_sync(0xFFFFFFFFu, dot, o);
    }

    if (lane == 0) {
        float aii = __ldg(adj + (size_t)row * N_CITIES + row);
        float xi  = __ldg(x + row);
        float s   = (2.0f * rs + aii) * xi - dot;
        out[row] = (s > 0.0f) ? 1.0f : ((s < 0.0f) ? -1.0f : 0.0f);
    }
}

extern "C" void kernel_launch(void* const* d_in, const int* in_sizes, int n_in,
                              void* d_out, int out_size) {
    const float* adj = (const float*)d_in[0];   // [8192, 8192] fp32 row-major
    const float* x   = (const float*)d_in[1];   // [8192] fp32
    float* out       = (float*)d_out;           // [8192] fp32

    hopfield_fused_kernel<<<N_CITIES / ROWS_PER_BLOCK, THREADS>>>(adj, x, out);
}